// round 1
// baseline (speedup 1.0000x reference)
#include <cuda_runtime.h>

// Problem constants (fixed shapes)
#define TT 128   // time
#define HH 16    // heads
#define NN 64    // batch
#define CC 256   // classes
#define S_TGT 64
#define SS 129   // 2*S_TGT + 1 states
#define NJ 65    // needed classes per n: blank + 64 targets

#define LOG_TINYF (-87.3365479f)
#define TINYF (1.17549435e-38f)

// Scratch: LW table, T*N*65 floats (~2.1 MB). Device global (no allocs allowed).
__device__ float g_G[TT * NN * NJ];

__device__ __forceinline__ float logadd(float a, float b) {
    // matches reference: x + log1p(exp(y-x)), x=max, y=min
    float mx = fmaxf(a, b);
    float mn = fminf(a, b);
    return mx + __logf(1.0f + __expf(mn - mx));
}

// ---------------------------------------------------------------------------
// Kernel A: G[t][n][j] = log(max(sum_h exp(classify[t][h][n][c_j] + mask[t][h][n]), TINY))
// c_0 = blank(0), c_j = targets[n][j-1]
// grid (NN, TT), block 96 (65 active lanes)
// ---------------------------------------------------------------------------
__global__ __launch_bounds__(96) void lw_kernel(
    const float* __restrict__ mask,      // [T][H][N]
    const float* __restrict__ classify,  // [T][H][N][C]
    const int*   __restrict__ targets)   // [N][64]
{
    int n = blockIdx.x;
    int t = blockIdx.y;
    int j = threadIdx.x;
    if (j >= NJ) return;

    int c = (j == 0) ? 0 : targets[n * S_TGT + (j - 1)];

    const float* clsbase = classify + ((size_t)t * HH * NN + n) * CC + c;
    const float* mbase   = mask + (size_t)t * HH * NN + n;

    float sum = 0.0f;
#pragma unroll
    for (int h = 0; h < HH; ++h) {
        float x = clsbase[(size_t)h * NN * CC] + mbase[h * NN];
        sum += __expf(x);
    }
    g_G[(t * NN + n) * NJ + j] = __logf(fmaxf(sum, TINYF));
}

// ---------------------------------------------------------------------------
// Kernel B: per-n clamped CTC forward recursion over alpha[s] only.
//   hs_i[s]  = max(alpha[s] + LW_i[et[s]], LOG_TINY), unc override -> LOG_TINY
//   alpha[s] = logadd(hs[s], hs[s-1] (,hs[s-2] if skip))   (i = 0..126)
//   res[s]   = alpha[s] + LW_127[et[s]]
//   loss     = -logadd(res[2L], res[2L-1]) / L
// grid NN, block 160 (129 active states; extra lanes duplicate s=128)
// ---------------------------------------------------------------------------
__global__ __launch_bounds__(160) void rec_kernel(
    const int* __restrict__ targets,   // [N][64]
    const int* __restrict__ tlen,      // [N]
    float* __restrict__ out)           // [N]
{
    __shared__ float Gs[TT][NJ + 1];   // 128 x 66 floats (padded)
    __shared__ float hsb[2][SS + 3];   // double-buffered hs
    __shared__ int   ccv[TT];          // ccv[i] = cc[i+1], i = 0..126
    __shared__ int   tg[S_TGT];

    int n = blockIdx.x;
    int tid = threadIdx.x;

    if (tid < S_TGT) tg[tid] = targets[n * S_TGT + tid];
    __syncthreads();

    // Load all LW rows for this n into smem (coalesced 65-float segments).
    for (int idx = tid; idx < TT * NJ; idx += blockDim.x) {
        int t = idx / NJ;
        int j = idx - t * NJ;
        Gs[t][j] = g_G[(t * NN + n) * NJ + j];
    }

    // cc prefix (serial, thread 0; overlaps with Gs loads from other threads).
    // cc[1]=2; cc[i+1] = cc[i] + 1 + msf[i-1], msf[k]= (k odd) && tg[(k+1)/2]!=tg[(k-1)/2]
    if (tid == 0) {
        int c = 2;
        ccv[0] = 2;
        for (int i = 1; i < 127; ++i) {
            int k = i - 1;
            int sk = 0;
            if (k & 1) sk = (tg[(k + 1) >> 1] != tg[(k - 1) >> 1]) ? 1 : 0;
            c += 1 + sk;
            ccv[i] = c;
        }
    }

    int s = min(tid, SS - 1);               // lanes >=129 duplicate s=128 (benign)
    int jm = (s & 1) ? ((s + 1) >> 1) : 0;  // gather index: even->blank, odd->target
    bool sk = false;
    if ((s & 1) && s >= 3) sk = (tg[(s - 1) >> 1] != tg[(s - 3) >> 1]);

    __syncthreads();

    float alpha = (s < 2) ? 0.0f : -1e30f;  // p0: states >=2 start clamped
    float lw = Gs[0][jm];

    for (int i = 0; i < 127; ++i) {
        float hs = fmaxf(alpha + lw, LOG_TINYF);
        if (s > ccv[i]) hs = LOG_TINYF;     // unreachable-state mask
        lw = Gs[i + 1][jm];                 // prefetch next LW (i=126 -> row 127 used after loop)

        float* buf = hsb[i & 1];
        buf[s] = hs;
        __syncthreads();

        float hm1 = buf[(s >= 1) ? s - 1 : 0];
        float hm2 = buf[(s >= 2) ? s - 2 : 0];
        float na;
        if (s == 0) {
            na = hs;
        } else {
            float t1 = logadd(hs, hm1);
            na = sk ? logadd(t1, hm2) : t1;
        }
        alpha = na;
    }

    // Final: res[s] = alpha + LW_127[et[s]]  (stable h-reduction folds into LW exactly)
    float resv = alpha + lw;  // lw == Gs[127][jm] after last iteration
    __syncthreads();          // all reads of hsb done before reuse
    hsb[0][s] = resv;
    __syncthreads();

    if (tid == 0) {
        int L = tlen[n];
        float g1 = hsb[0][2 * L];
        float g2 = hsb[0][2 * L - 1];
        out[n] = -logadd(g1, g2) / (float)L;
    }
}

// ---------------------------------------------------------------------------
extern "C" void kernel_launch(void* const* d_in, const int* in_sizes, int n_in,
                              void* d_out, int out_size)
{
    const float* mask     = (const float*)d_in[0];  // [128][16][64]
    const float* classify = (const float*)d_in[1];  // [128][16][64][256]
    const int*   targets  = (const int*)d_in[2];    // [64][64]
    // d_in[3] = input_lengths (unused by reference math)
    const int*   tlen     = (const int*)d_in[4];    // [64]
    float* out = (float*)d_out;

    dim3 gridA(NN, TT);
    lw_kernel<<<gridA, 96>>>(mask, classify, targets);
    rec_kernel<<<NN, 160>>>(targets, tlen, out);
}

// round 2
// speedup vs baseline: 1.1296x; 1.1296x over previous
#include <cuda_runtime.h>

// Problem constants (fixed shapes)
#define TT 128   // time
#define HH 16    // heads
#define NN 64    // batch
#define CC 256   // classes
#define S_TGT 64
#define SS 129   // 2*S_TGT + 1 states
#define NJ 65    // needed classes per n: blank + 64 targets
#define GROW 68  // padded row stride (16B aligned: 68*4=272=17*16)

#define LOG_TINYF (-87.3365479f)
#define TINYF (1.17549435e-38f)
#define NEGBIG (-1e30f)

// Scratch: LW table [T][N][GROW]. Device global (no allocs allowed).
__device__ float g_G[TT * NN * GROW];

__device__ __forceinline__ float logadd2(float a, float b) {
    float mx = fmaxf(a, b);
    float mn = fminf(a, b);
    return mx + __logf(1.0f + __expf(mn - mx));
}

// 3-term logsumexp (used for odd states; third arg may be NEGBIG filler)
__device__ __forceinline__ float lse3(float a, float b, float c) {
    float m = fmaxf(fmaxf(a, b), c);
    float s = __expf(a - m) + __expf(b - m) + __expf(c - m);
    return m + __logf(s);
}

// ---------------------------------------------------------------------------
// Kernel A: G[t][n][j] = log(max(sum_h exp(classify[t][h][n][c_j] + mask[t][h][n]), TINY))
// c_0 = blank(0), c_j = targets[n][j-1]
// grid (NN, TT), block 96 (65 active lanes)
// ---------------------------------------------------------------------------
__global__ __launch_bounds__(96) void lw_kernel(
    const float* __restrict__ mask,      // [T][H][N]
    const float* __restrict__ classify,  // [T][H][N][C]
    const int*   __restrict__ targets)   // [N][64]
{
    int n = blockIdx.x;
    int t = blockIdx.y;
    int j = threadIdx.x;
    if (j >= NJ) return;

    int c = (j == 0) ? 0 : targets[n * S_TGT + (j - 1)];

    const float* clsbase = classify + ((size_t)t * HH * NN + n) * CC + c;
    const float* mbase   = mask + (size_t)t * HH * NN + n;

    float sum = 0.0f;
#pragma unroll
    for (int h = 0; h < HH; ++h) {
        float x = clsbase[(size_t)h * NN * CC] + mbase[h * NN];
        sum += __expf(x);
    }
    g_G[(t * NN + n) * GROW + j] = __logf(fmaxf(sum, TINYF));
}

// ---------------------------------------------------------------------------
// Kernel B: per-n CTC forward recursion, single-warp, 4 states/lane.
// Lane L holds states s = 4L..4L+3; lane 31 additionally s=128.
// Cross-lane dependency: only hs[4L-1] (prev lane's h3) via one shfl_up.
// Warps 1..4 only help stage the LW table to smem, then exit.
// ---------------------------------------------------------------------------
__global__ __launch_bounds__(160) void rec_kernel(
    const int* __restrict__ targets,   // [N][64]
    const int* __restrict__ tlen,      // [N]
    float* __restrict__ out)           // [N]
{
    __shared__ float Gs[TT][GROW];     // 128 x 68 floats (34.8 KB)
    __shared__ int   ccv[TT];          // ccv[i], i = 0..126
    __shared__ int   tg[S_TGT];
    __shared__ float resb[SS];

    int n = blockIdx.x;
    int tid = threadIdx.x;

    if (tid < S_TGT) tg[tid] = targets[n * S_TGT + tid];

    // cc prefix (serial on thread 0; overlaps with loads by other warps)
    if (tid == 0) {
        int c = 2;
        ccv[0] = 2;
        for (int i = 1; i < 127; ++i) {
            int k = i - 1;
            int sk = 0;
            if (k & 1) sk = (tg[(k + 1) >> 1] != tg[(k - 1) >> 1]) ? 1 : 0;
            c += 1 + sk;
            ccv[i] = c;
        }
    }

    // Stage LW table to smem, float4, coalesced. 2176 float4 / 160 threads.
    {
        const float4* src = (const float4*)(g_G + (size_t)n * GROW);
        float4* dst = (float4*)(&Gs[0][0]);
        // row r of this n lives at g_G[(r*NN + n)*GROW]; float4 index base r*NN*17
        for (int idx = tid; idx < TT * (GROW / 4); idx += 160) {
            int r = idx / (GROW / 4);
            int q = idx - r * (GROW / 4);
            dst[r * (GROW / 4) + q] = src[(size_t)r * NN * (GROW / 4) + q];
        }
    }
    __syncthreads();
    if (tid >= 32) return;   // loader warps done; no more block syncs below

    int lane = tid;
    int s0 = 4 * lane;                       // states s0..s0+3 (+128 on lane 31)
    // skip flags (odd states only). s1=4L+1: skip iff L>=1 && tg[2L]!=tg[2L-1]
    //                               s3=4L+3: skip iff tg[2L+1]!=tg[2L]
    bool sk1 = (lane >= 1) && (tg[2 * lane] != tg[2 * lane - 1]);
    bool sk3 = (tg[2 * lane + 1] != tg[2 * lane]);

    float a0 = (lane == 0) ? 0.0f : NEGBIG;  // s<2 start at 0
    float a1 = (lane == 0) ? 0.0f : NEGBIG;
    float a2 = NEGBIG, a3 = NEGBIG, a4 = NEGBIG;

    int j1 = 2 * lane + 1;   // LW column for s1
    int j2 = 2 * lane + 2;   // LW column for s3
    float lwB = Gs[0][0];
    float lw1 = Gs[0][j1];
    float lw2 = Gs[0][j2];

#pragma unroll 1
    for (int i = 0; i < 127; ++i) {
        int cc = ccv[i];
        float h0 = fmaxf(a0 + lwB, LOG_TINYF);
        float h1 = fmaxf(a1 + lw1, LOG_TINYF);
        float h2 = fmaxf(a2 + lwB, LOG_TINYF);
        float h3 = fmaxf(a3 + lw2, LOG_TINYF);
        float h4 = fmaxf(a4 + lwB, LOG_TINYF);
        if (s0     > cc) h0 = LOG_TINYF;
        if (s0 + 1 > cc) h1 = LOG_TINYF;
        if (s0 + 2 > cc) h2 = LOG_TINYF;
        if (s0 + 3 > cc) h3 = LOG_TINYF;
        if (128    > cc) h4 = LOG_TINYF;

        // prefetch next-row LW (row 127 used after the loop)
        lwB = Gs[i + 1][0];
        lw1 = Gs[i + 1][j1];
        lw2 = Gs[i + 1][j2];

        float h3p = __shfl_up_sync(0xffffffffu, h3, 1);
        if (lane == 0) h3p = NEGBIG;

        float e1 = sk1 ? h3p : NEGBIG;
        float e3 = sk3 ? h1  : NEGBIG;
        a0 = logadd2(h0, h3p);           // lane 0: logadd2(h0, NEGBIG) == h0
        a1 = lse3(h1, h0, e1);
        a2 = logadd2(h2, h1);
        a3 = lse3(h3, h2, e3);
        a4 = logadd2(h4, h3);            // meaningful only on lane 31
    }

    // Final: res[s] = alpha + LW_127[et[s]]  (lw* hold row 127)
    resb[s0]     = a0 + lwB;
    resb[s0 + 1] = a1 + lw1;
    resb[s0 + 2] = a2 + lwB;
    resb[s0 + 3] = a3 + lw2;
    if (lane == 31) resb[128] = a4 + lwB;
    __syncwarp();

    if (lane == 0) {
        int L = tlen[n];
        float g1 = resb[2 * L];
        float g2 = resb[2 * L - 1];
        out[n] = -logadd2(g1, g2) / (float)L;
    }
}

// ---------------------------------------------------------------------------
extern "C" void kernel_launch(void* const* d_in, const int* in_sizes, int n_in,
                              void* d_out, int out_size)
{
    const float* mask     = (const float*)d_in[0];  // [128][16][64]
    const float* classify = (const float*)d_in[1];  // [128][16][64][256]
    const int*   targets  = (const int*)d_in[2];    // [64][64]
    // d_in[3] = input_lengths (unused by reference math)
    const int*   tlen     = (const int*)d_in[4];    // [64]
    float* out = (float*)d_out;

    dim3 gridA(NN, TT);
    lw_kernel<<<gridA, 96>>>(mask, classify, targets);
    rec_kernel<<<NN, 160>>>(targets, tlen, out);
}

// round 3
// speedup vs baseline: 1.4118x; 1.2498x over previous
#include <cuda_runtime.h>

// Problem constants (fixed shapes)
#define TT 128   // time
#define HH 16    // heads
#define NN 64    // batch
#define CC 256   // classes
#define S_TGT 64
#define SS 129   // 2*S_TGT + 1 states
#define NJ 65    // needed classes per n: blank + 64 targets
#define GROW 68  // padded row stride (16B aligned: 68*4=272)

#define LOG_TINYF (-87.3365479f)
#define TINYF (1.17549435e-38f)

// Scratch: W table (linear domain), [T][N][GROW]. Device global (no allocs allowed).
__device__ float g_G[TT * NN * GROW];

__device__ __forceinline__ float logadd2(float a, float b) {
    float mx = fmaxf(a, b);
    float mn = fminf(a, b);
    return mx + __logf(1.0f + __expf(mn - mx));
}

// ---------------------------------------------------------------------------
// Kernel A: W[t][n][j] = max(sum_h exp(classify[t][h][n][c_j] + mask[t][h][n]), TINY)
// c_0 = blank(0), c_j = targets[n][j-1]. NO log — consumer works in linear domain.
// grid (NN, TT), block 96 (65 active lanes)
// ---------------------------------------------------------------------------
__global__ __launch_bounds__(96) void lw_kernel(
    const float* __restrict__ mask,      // [T][H][N]
    const float* __restrict__ classify,  // [T][H][N][C]
    const int*   __restrict__ targets)   // [N][64]
{
    int n = blockIdx.x;
    int t = blockIdx.y;
    int j = threadIdx.x;
    if (j >= NJ) return;

    int c = (j == 0) ? 0 : targets[n * S_TGT + (j - 1)];

    const float* clsbase = classify + ((size_t)t * HH * NN + n) * CC + c;
    const float* mbase   = mask + (size_t)t * HH * NN + n;

    float sum = 0.0f;
#pragma unroll
    for (int h = 0; h < HH; ++h) {
        float x = clsbase[(size_t)h * NN * CC] + mbase[h * NN];
        sum += __expf(x);
    }
    g_G[(t * NN + n) * GROW + j] = fmaxf(sum, TINYF);
}

// ---------------------------------------------------------------------------
// Kernel B: per-n CTC forward recursion in the LINEAR domain.
// Single warp does the recursion, 4 states/lane (lane 31 carries s=128 too).
// Cross-lane dep per step: H[4L-1] -> one shfl_up. No transcendentals in loop.
// Warps 1..4 only stage the W table to smem, then exit.
// ---------------------------------------------------------------------------
__global__ __launch_bounds__(160) void rec_kernel(
    const int* __restrict__ targets,   // [N][64]
    const int* __restrict__ tlen,      // [N]
    float* __restrict__ out)           // [N]
{
    __shared__ float Gs[TT][GROW];     // 128 x 68 floats (34.8 KB)
    __shared__ int   ccv[TT];          // ccv[i], i = 0..126
    __shared__ int   tg[S_TGT];
    __shared__ float resb[SS];

    int n = blockIdx.x;
    int tid = threadIdx.x;

    if (tid < S_TGT) tg[tid] = targets[n * S_TGT + tid];

    // cc prefix (serial on thread 0; overlaps with staging by other warps)
    if (tid == 0) {
        int c = 2;
        ccv[0] = 2;
        for (int i = 1; i < 127; ++i) {
            int k = i - 1;
            int sk = 0;
            if (k & 1) sk = (tg[(k + 1) >> 1] != tg[(k - 1) >> 1]) ? 1 : 0;
            c += 1 + sk;
            ccv[i] = c;
        }
    }

    // Stage W table to smem, float4, coalesced. 2176 float4 / 160 threads.
    {
        const float4* src = (const float4*)(g_G + (size_t)n * GROW);
        float4* dst = (float4*)(&Gs[0][0]);
        for (int idx = tid; idx < TT * (GROW / 4); idx += 160) {
            int r = idx / (GROW / 4);
            int q = idx - r * (GROW / 4);
            dst[r * (GROW / 4) + q] = src[(size_t)r * NN * (GROW / 4) + q];
        }
    }
    __syncthreads();
    if (tid >= 32) return;   // loader warps done

    int lane = tid;
    int s0 = 4 * lane;                       // states s0..s0+3 (+128 on lane 31)
    bool sk1 = (lane >= 1) && (tg[2 * lane] != tg[2 * lane - 1]);
    bool sk3 = (tg[2 * lane + 1] != tg[2 * lane]);

    // linear-domain alpha: exp(0)=1 for s<2, exp(-inf)=0 otherwise
    float A0 = (lane == 0) ? 1.0f : 0.0f;
    float A1 = (lane == 0) ? 1.0f : 0.0f;
    float A2 = 0.0f, A3 = 0.0f, A4 = 0.0f;

    int j1 = 2 * lane + 1;   // W column for s1
    int j2 = 2 * lane + 2;   // W column for s3
    float WB = Gs[0][0];
    float W1 = Gs[0][j1];
    float W2 = Gs[0][j2];

#pragma unroll 1
    for (int i = 0; i < 127; ++i) {
        int cc = ccv[i];
        float H0 = fmaxf(A0 * WB, TINYF);
        float H1 = fmaxf(A1 * W1, TINYF);
        float H2 = fmaxf(A2 * WB, TINYF);
        float H3 = fmaxf(A3 * W2, TINYF);
        float H4 = fmaxf(A4 * WB, TINYF);
        if (s0     > cc) H0 = TINYF;
        if (s0 + 1 > cc) H1 = TINYF;
        if (s0 + 2 > cc) H2 = TINYF;
        if (s0 + 3 > cc) H3 = TINYF;
        if (128    > cc) H4 = TINYF;

        // prefetch next-row W (row 127 consumed after the loop)
        WB = Gs[i + 1][0];
        W1 = Gs[i + 1][j1];
        W2 = Gs[i + 1][j2];

        float H3p = __shfl_up_sync(0xffffffffu, H3, 1);
        if (lane == 0) H3p = 0.0f;

        A0 = H0 + H3p;
        A1 = H1 + H0 + (sk1 ? H3p : 0.0f);
        A2 = H2 + H1;
        A3 = H3 + H2 + (sk3 ? H1 : 0.0f);
        A4 = H4 + H3;                    // meaningful only on lane 31
    }

    // Final (log domain once): res[s] = log(A) + log(W_127[et[s]]); A >= TINY, W >= TINY.
    resb[s0]     = __logf(A0) + __logf(WB);
    resb[s0 + 1] = __logf(A1) + __logf(W1);
    resb[s0 + 2] = __logf(A2) + __logf(WB);
    resb[s0 + 3] = __logf(A3) + __logf(W2);
    if (lane == 31) resb[128] = __logf(A4) + __logf(WB);
    __syncwarp();

    if (lane == 0) {
        int L = tlen[n];
        float g1 = resb[2 * L];
        float g2 = resb[2 * L - 1];
        out[n] = -logadd2(g1, g2) / (float)L;
    }
}

// ---------------------------------------------------------------------------
extern "C" void kernel_launch(void* const* d_in, const int* in_sizes, int n_in,
                              void* d_out, int out_size)
{
    const float* mask     = (const float*)d_in[0];  // [128][16][64]
    const float* classify = (const float*)d_in[1];  // [128][16][64][256]
    const int*   targets  = (const int*)d_in[2];    // [64][64]
    // d_in[3] = input_lengths (unused by reference math)
    const int*   tlen     = (const int*)d_in[4];    // [64]
    float* out = (float*)d_out;

    dim3 gridA(NN, TT);
    lw_kernel<<<gridA, 96>>>(mask, classify, targets);
    rec_kernel<<<NN, 160>>>(targets, tlen, out);
}

// round 4
// speedup vs baseline: 1.4898x; 1.0553x over previous
#include <cuda_runtime.h>

// Problem constants (fixed shapes)
#define TT 128   // time
#define HH 16    // heads
#define NN 64    // batch
#define CC 256   // classes
#define S_TGT 64
#define SS 129   // 2*S_TGT + 1 states
#define NJ 65    // needed classes per n: blank + 64 targets
#define GROW 68  // padded row stride (16B aligned: 68*4=272)

#define LOG_TINYF (-87.3365479f)
#define TINYF (1.17549435e-38f)

// Scratch: W table (linear domain), [T][N][GROW]. Device global (no allocs allowed).
__device__ float g_G[TT * NN * GROW];

__device__ __forceinline__ float logadd2(float a, float b) {
    float mx = fmaxf(a, b);
    float mn = fminf(a, b);
    return mx + __logf(1.0f + __expf(mn - mx));
}

// ---------------------------------------------------------------------------
// Kernel A: W[t][n][j] = max(sum_h exp(classify[t][h][n][c_j] + mask[t][h][n]), TINY)
// c_0 = blank(0), c_j = targets[n][j-1]. Linear domain (no log).
// grid (NN, TT), block 96 (65 active lanes)
// ---------------------------------------------------------------------------
__global__ __launch_bounds__(96) void lw_kernel(
    const float* __restrict__ mask,      // [T][H][N]
    const float* __restrict__ classify,  // [T][H][N][C]
    const int*   __restrict__ targets)   // [N][64]
{
    int n = blockIdx.x;
    int t = blockIdx.y;
    int j = threadIdx.x;
    if (j >= NJ) return;

    int c = (j == 0) ? 0 : targets[n * S_TGT + (j - 1)];

    const float* clsbase = classify + ((size_t)t * HH * NN + n) * CC + c;
    const float* mbase   = mask + (size_t)t * HH * NN + n;

    float sum = 0.0f;
#pragma unroll
    for (int h = 0; h < HH; ++h) {
        float x = __ldcs(clsbase + (size_t)h * NN * CC) + mbase[h * NN];
        sum += __expf(x);
    }
    g_G[(t * NN + n) * GROW + j] = fmaxf(sum, TINYF);
}

// ---------------------------------------------------------------------------
// Kernel B: per-n CTC forward recursion, linear domain, single recursion warp.
// Lane L holds states 4L..4L+3 (+ s=128 on lane 31). One shfl_up per iter,
// issued at the top of the body and consumed at the bottom. Unreachable-state
// masking folded into the W operands via precomputed per-state threshold steps.
// Warps 1..4 stage the W table; warp 0 does setup concurrently.
// ---------------------------------------------------------------------------
__global__ __launch_bounds__(160) void rec_kernel(
    const int* __restrict__ targets,   // [N][64]
    const int* __restrict__ tlen,      // [N]
    float* __restrict__ out)           // [N]
{
    __shared__ float Gs[TT][GROW];     // 128 x 68 floats (34.8 KB)
    __shared__ int   Dsh[S_TGT];       // D[m] = sum_{j<=m} d[j], d[j]=(tg[j]!=tg[j-1])
    __shared__ float resb[SS];

    int n = blockIdx.x;
    int tid = threadIdx.x;

    // ---- warps 1..4: stage W table (2176 float4, coalesced) ----
    if (tid >= 32) {
        const float4* src = (const float4*)(g_G + (size_t)n * GROW);
        float4* dst = (float4*)(&Gs[0][0]);
        for (int idx = tid - 32; idx < TT * (GROW / 4); idx += 128) {
            int r = idx / (GROW / 4);
            int q = idx - r * (GROW / 4);
            dst[r * (GROW / 4) + q] = src[(size_t)r * NN * (GROW / 4) + q];
        }
        __syncthreads();   // staging complete
        return;
    }

    // ---- warp 0: setup (runs concurrently with staging) ----
    int lane = tid;
    int s0 = 4 * lane;

    // d'[2l] = (tg[2l]!=tg[2l-1]) (l>=1), d'[2l+1] = (tg[2l+1]!=tg[2l])
    int tgA = targets[n * S_TGT + 2 * lane];
    int tgB = targets[n * S_TGT + 2 * lane + 1];
    int tgP = __shfl_up_sync(0xffffffffu, tgB, 1);   // tg[2l-1] for l>=1
    int d0 = (lane >= 1) ? (tgA != tgP ? 1 : 0) : 0;
    int d1 = (tgB != tgA) ? 1 : 0;
    bool sk1 = (d0 != 0);    // valid for lane>=1 (lane 0 never uses it)
    bool sk3 = (d1 != 0);

    // inclusive pair-scan -> D
    int sl = d0 + d1;
#pragma unroll
    for (int off = 1; off < 32; off <<= 1) {
        int v = __shfl_up_sync(0xffffffffu, sl, off);
        if (lane >= off) sl += v;
    }
    Dsh[2 * lane + 1] = sl;        // D[2l+1]
    Dsh[2 * lane]     = sl - d1;   // D[2l]
    __syncwarp();

    // thresholds: i_s = min{ i : 2 + i + D[i>>1] >= s }  (0 if s<=2)
    int sv[5] = { s0, s0 + 1, s0 + 2, s0 + 3, 128 };
    int lo[5], hi[5];
#pragma unroll
    for (int k = 0; k < 5; ++k) { lo[k] = 0; hi[k] = 126; }
#pragma unroll
    for (int it = 0; it < 7; ++it) {
#pragma unroll
        for (int k = 0; k < 5; ++k) {
            int mid = (lo[k] + hi[k]) >> 1;
            int f = 2 + mid + Dsh[mid >> 1];
            if (f >= sv[k]) hi[k] = mid; else lo[k] = mid + 1;
        }
    }
    int th0 = (sv[0] <= 2) ? 0 : lo[0];
    int th1 = (sv[1] <= 2) ? 0 : lo[1];
    int th2 = (sv[2] <= 2) ? 0 : lo[2];
    int th3 = lo[3];
    int th4 = lo[4];

    float A0 = (lane == 0) ? 1.0f : 0.0f;   // exp(0)=1 for s<2
    float A1 = (lane == 0) ? 1.0f : 0.0f;
    float A2 = 0.0f, A3 = 0.0f, A4 = 0.0f;

    int j1 = 2 * lane + 1;
    int j2 = 2 * lane + 2;

    __syncthreads();   // wait for staging

    // prefetch row 0 (raw + masked for i=0: masked iff 0 < th)
    float WB = Gs[0][0];
    float W1 = Gs[0][j1];
    float W2 = Gs[0][j2];
    float WB0m = (0 < th0) ? 0.0f : WB;
    float W1m  = (0 < th1) ? 0.0f : W1;
    float WB2m = (0 < th2) ? 0.0f : WB;
    float W2m  = (0 < th3) ? 0.0f : W2;
    float WB4m = (0 < th4) ? 0.0f : WB;

#pragma unroll 2
    for (int i = 0; i < 127; ++i) {
        // H3 first -> fire the shfl immediately
        float H3 = fmaxf(A3 * W2m, TINYF);
        float H3p = __shfl_up_sync(0xffffffffu, H3, 1);

        float H0 = fmaxf(A0 * WB0m, TINYF);
        float H1 = fmaxf(A1 * W1m, TINYF);
        float H2 = fmaxf(A2 * WB2m, TINYF);
        float H4 = fmaxf(A4 * WB4m, TINYF);

        // prefetch + mask next row (off the critical chain, under shfl latency)
        WB = Gs[i + 1][0];
        W1 = Gs[i + 1][j1];
        W2 = Gs[i + 1][j2];
        int in = i + 1;
        WB0m = (in < th0) ? 0.0f : WB;
        W1m  = (in < th1) ? 0.0f : W1;
        WB2m = (in < th2) ? 0.0f : WB;
        W2m  = (in < th3) ? 0.0f : W2;
        WB4m = (in < th4) ? 0.0f : WB;

        // local combines (shfl-independent)
        A2 = H2 + H1;
        A3 = H3 + H2 + (sk3 ? H1 : 0.0f);
        A4 = H4 + H3;                       // meaningful on lane 31 only

        // shfl-dependent combines last
        if (lane == 0) H3p = 0.0f;
        A0 = H0 + H3p;
        A1 = (H1 + H0) + (sk1 ? H3p : 0.0f);
    }

    // Final: res[s] = log(A) + log(W_127[et[s]]) ; raw row-127 values in WB/W1/W2.
    resb[s0]     = __logf(A0) + __logf(WB);
    resb[s0 + 1] = __logf(A1) + __logf(W1);
    resb[s0 + 2] = __logf(A2) + __logf(WB);
    resb[s0 + 3] = __logf(A3) + __logf(W2);
    if (lane == 31) resb[128] = __logf(A4) + __logf(WB);
    __syncwarp();

    if (lane == 0) {
        int L = tlen[n];
        float g1 = resb[2 * L];
        float g2 = resb[2 * L - 1];
        out[n] = -logadd2(g1, g2) / (float)L;
    }
}

// ---------------------------------------------------------------------------
extern "C" void kernel_launch(void* const* d_in, const int* in_sizes, int n_in,
                              void* d_out, int out_size)
{
    const float* mask     = (const float*)d_in[0];  // [128][16][64]
    const float* classify = (const float*)d_in[1];  // [128][16][64][256]
    const int*   targets  = (const int*)d_in[2];    // [64][64]
    // d_in[3] = input_lengths (unused by reference math)
    const int*   tlen     = (const int*)d_in[4];    // [64]
    float* out = (float*)d_out;

    dim3 gridA(NN, TT);
    lw_kernel<<<gridA, 96>>>(mask, classify, targets);
    rec_kernel<<<NN, 160>>>(targets, tlen, out);
}